// round 2
// baseline (speedup 1.0000x reference)
#include <cuda_runtime.h>
#include <cstdint>

// Gauss-Legendre tables for n = 1..5 (numpy-double -> float32 cast).
__constant__ float XI_TAB[5][5] = {
    { 0.0f, 0.f, 0.f, 0.f, 0.f },
    { -0.5773502691896258f, 0.5773502691896258f, 0.f, 0.f, 0.f },
    { -0.7745966692414834f, 0.0f, 0.7745966692414834f, 0.f, 0.f },
    { -0.8611363115940526f, -0.3399810435848563f, 0.3399810435848563f, 0.8611363115940526f, 0.f },
    { 0.0f, -0.5384693101056831f, 0.5384693101056831f, -0.9061798459386640f, 0.9061798459386640f },
};
__constant__ float W_TAB[5][5] = {
    { 2.0f, 0.f, 0.f, 0.f, 0.f },
    { 1.0f, 1.0f, 0.f, 0.f, 0.f },
    { 0.5555555555555556f, 0.8888888888888889f, 0.5555555555555556f, 0.f, 0.f },
    { 0.3478548451374538f, 0.6521451548625461f, 0.6521451548625461f, 0.3478548451374538f, 0.f },
    { 0.5688888888888889f, 0.4786286704993665f, 0.4786286704993665f, 0.2369268850561891f, 0.2369268850561891f },
};

// One thread per element. Explicit round-to-nearest intrinsics everywhere:
// the reference's fp32 op sequence must be reproduced exactly — x1 ~ 4e6
// makes (x_g - x1) a catastrophic-cancellation term whose quantized value
// feeds ref/N/interpol, so FMA contraction would change results by O(0.1).
template <int G>
__global__ void __launch_bounds__(256) meshnn1d_kernel(
    const float* __restrict__ coords,
    const float* __restrict__ vals,
    const int*   __restrict__ conn,    // [E,2] int32 (jax x64 disabled), 1-based
    float* __restrict__ out,           // [3, E, G] : interpol | x_g | detJ_w
    int E)
{
    int e = blockIdx.x * blockDim.x + threadIdx.x;
    if (e >= E) return;

    // vectorized 8B connectivity load
    int2 c = reinterpret_cast<const int2*>(conn)[e];
    int i1 = c.x - 1;
    int i2 = c.y - 1;

    float x1 = coords[i1];
    float x2 = coords[i2];
    float v1 = vals[i1];
    float v2 = vals[i2];

    float dx   = __fsub_rn(x2, x1);
    float detJ = __fmul_rn(dx, 0.5f);

    size_t EG   = (size_t)E * G;
    size_t base = (size_t)e * G;
    float* out_interp = out;
    float* out_xg     = out + EG;
    float* out_djw    = out + 2 * EG;

#pragma unroll
    for (int g = 0; g < G; ++g) {
        float xi = XI_TAB[G - 1][g];
        float w  = W_TAB[G - 1][g];

        // x_g = x1 + (xi + 1) * (x2 - x1) * 0.5   (left-to-right roundings)
        float t   = __fmul_rn(__fmul_rn(__fadd_rn(xi, 1.0f), dx), 0.5f);
        float x_g = __fadd_rn(x1, t);

        // ref = 2*(x_g - x1)/dx - 1
        float num = __fmul_rn(2.0f, __fsub_rn(x_g, x1));
        float ref = __fsub_rn(__fdiv_rn(num, dx), 1.0f);

        // N0 = -0.5*ref + 0.5 ; N1 = 0.5*ref + 0.5
        float N0 = __fadd_rn(__fmul_rn(-0.5f, ref), 0.5f);
        float N1 = __fadd_rn(__fmul_rn(0.5f, ref), 0.5f);

        float interp = __fadd_rn(__fmul_rn(N0, v1), __fmul_rn(N1, v2));
        float djw    = __fmul_rn(detJ, w);

        out_interp[base + g] = interp;
        out_xg[base + g]     = x_g;
        out_djw[base + g]    = djw;
    }
}

extern "C" void kernel_launch(void* const* d_in, const int* in_sizes, int n_in,
                              void* d_out, int out_size)
{
    const float* coords = (const float*)d_in[0];
    const float* vals   = (const float*)d_in[1];
    const int*   conn   = (const int*)d_in[2];
    float*       out    = (float*)d_out;

    int E = in_sizes[2] / 2;
    int G = (E > 0) ? (int)((long long)out_size / (3LL * E)) : 3;
    if (G < 1) G = 1;
    if (G > 5) G = 5;

    int threads = 256;
    int blocks  = (E + threads - 1) / threads;

    switch (G) {
        case 1: meshnn1d_kernel<1><<<blocks, threads>>>(coords, vals, conn, out, E); break;
        case 2: meshnn1d_kernel<2><<<blocks, threads>>>(coords, vals, conn, out, E); break;
        case 3: meshnn1d_kernel<3><<<blocks, threads>>>(coords, vals, conn, out, E); break;
        case 4: meshnn1d_kernel<4><<<blocks, threads>>>(coords, vals, conn, out, E); break;
        case 5: meshnn1d_kernel<5><<<blocks, threads>>>(coords, vals, conn, out, E); break;
    }
}

// round 3
// speedup vs baseline: 1.4731x; 1.4731x over previous
#include <cuda_runtime.h>
#include <cstdint>

// Gauss-Legendre tables for n = 1..5 (numpy-double -> float32 cast).
__constant__ float XI_TAB[5][5] = {
    { 0.0f, 0.f, 0.f, 0.f, 0.f },
    { -0.5773502691896258f, 0.5773502691896258f, 0.f, 0.f, 0.f },
    { -0.7745966692414834f, 0.0f, 0.7745966692414834f, 0.f, 0.f },
    { -0.8611363115940526f, -0.3399810435848563f, 0.3399810435848563f, 0.8611363115940526f, 0.f },
    { 0.0f, -0.5384693101056831f, 0.5384693101056831f, -0.9061798459386640f, 0.9061798459386640f },
};
__constant__ float W_TAB[5][5] = {
    { 2.0f, 0.f, 0.f, 0.f, 0.f },
    { 1.0f, 1.0f, 0.f, 0.f, 0.f },
    { 0.5555555555555556f, 0.8888888888888889f, 0.5555555555555556f, 0.f, 0.f },
    { 0.3478548451374538f, 0.6521451548625461f, 0.6521451548625461f, 0.3478548451374538f, 0.f },
    { 0.5688888888888889f, 0.4786286704993665f, 0.4786286704993665f, 0.2369268850561891f, 0.2369268850561891f },
};

// Element-per-thread compute with exact reference rounding sequence
// (no FMA contraction — the x_g - x1 cancellation at x1 ~ 4e6 is
// catastrophic and must quantize identically to the reference).
// Outputs staged in shared memory, flushed with coalesced STG.128 —
// direct strided STG.32 cost 3x L1 wavefronts (R2 ncu: L1=72%, top pipe).
template <int G, int BLOCK>
__global__ void __launch_bounds__(BLOCK) meshnn1d_kernel(
    const float* __restrict__ coords,
    const float* __restrict__ vals,
    const int*   __restrict__ conn,    // [E,2] int32, 1-based
    float* __restrict__ out,           // [3, E, G] : interpol | x_g | detJ_w
    int E)
{
    __shared__ float s_buf[3][BLOCK * G];

    const int tid        = threadIdx.x;
    const int blockStart = blockIdx.x * BLOCK;
    const int e          = blockStart + tid;
    const int nElem      = min(BLOCK, E - blockStart);   // elements in this block

    if (tid < nElem) {
        int2 c = reinterpret_cast<const int2*>(conn)[e];
        int i1 = c.x - 1;
        int i2 = c.y - 1;

        float x1 = coords[i1];
        float x2 = coords[i2];
        float v1 = vals[i1];
        float v2 = vals[i2];

        float dx   = __fsub_rn(x2, x1);
        float detJ = __fmul_rn(dx, 0.5f);

#pragma unroll
        for (int g = 0; g < G; ++g) {
            float xi = XI_TAB[G - 1][g];
            float w  = W_TAB[G - 1][g];

            // x_g = x1 + (xi + 1) * dx * 0.5  (left-to-right roundings)
            float t   = __fmul_rn(__fmul_rn(__fadd_rn(xi, 1.0f), dx), 0.5f);
            float x_g = __fadd_rn(x1, t);

            // ref = 2*(x_g - x1)/dx - 1
            float num = __fmul_rn(2.0f, __fsub_rn(x_g, x1));
            float ref = __fsub_rn(__fdiv_rn(num, dx), 1.0f);

            float N0 = __fadd_rn(__fmul_rn(-0.5f, ref), 0.5f);
            float N1 = __fadd_rn(__fmul_rn(0.5f, ref), 0.5f);

            float interp = __fadd_rn(__fmul_rn(N0, v1), __fmul_rn(N1, v2));
            float djw    = __fmul_rn(detJ, w);

            s_buf[0][tid * G + g] = interp;   // stride G vs 32 banks: conflict-free
            s_buf[1][tid * G + g] = x_g;
            s_buf[2][tid * G + g] = djw;
        }
    }
    __syncthreads();

    const size_t EG   = (size_t)E * G;
    const size_t base = (size_t)blockStart * G;
    const int nFloats = nElem * G;

    if (nElem == BLOCK) {
        // Full block: vectorized coalesced flush. Alignment holds because
        // E*G*4 and blockStart*G*4 are both multiples of 16 here
        // (BLOCK*G % 4 == 0 and E*G % 4 == 0 for this problem family).
        constexpr int NV = BLOCK * G / 4;      // float4s per section
#pragma unroll
        for (int sec = 0; sec < 3; ++sec) {
            const float4* src = reinterpret_cast<const float4*>(&s_buf[sec][0]);
            size_t off = (size_t)sec * EG + base;
            if ((off & 3) == 0) {
                float4* dst = reinterpret_cast<float4*>(out + off);
                for (int i = tid; i < NV; i += BLOCK) dst[i] = src[i];
            } else {
                for (int i = tid; i < BLOCK * G; i += BLOCK)
                    out[off + i] = s_buf[sec][i];
            }
        }
    } else {
        // Tail block: scalar coalesced flush.
#pragma unroll
        for (int sec = 0; sec < 3; ++sec) {
            size_t off = (size_t)sec * EG + base;
            for (int i = tid; i < nFloats; i += BLOCK)
                out[off + i] = s_buf[sec][i];
        }
    }
}

template <int G>
static void launch(const float* coords, const float* vals, const int* conn,
                   float* out, int E)
{
    constexpr int BLOCK = 256;
    int blocks = (E + BLOCK - 1) / BLOCK;
    meshnn1d_kernel<G, BLOCK><<<blocks, BLOCK>>>(coords, vals, conn, out, E);
}

extern "C" void kernel_launch(void* const* d_in, const int* in_sizes, int n_in,
                              void* d_out, int out_size)
{
    const float* coords = (const float*)d_in[0];
    const float* vals   = (const float*)d_in[1];
    const int*   conn   = (const int*)d_in[2];
    float*       out    = (float*)d_out;

    int E = in_sizes[2] / 2;
    int G = (E > 0) ? (int)((long long)out_size / (3LL * E)) : 3;
    if (G < 1) G = 1;
    if (G > 5) G = 5;

    switch (G) {
        case 1: launch<1>(coords, vals, conn, out, E); break;
        case 2: launch<2>(coords, vals, conn, out, E); break;
        case 3: launch<3>(coords, vals, conn, out, E); break;
        case 4: launch<4>(coords, vals, conn, out, E); break;
        case 5: launch<5>(coords, vals, conn, out, E); break;
    }
}